// round 11
// baseline (speedup 1.0000x reference)
#include <cuda_runtime.h>
#include <cuda_fp16.h>
#include <cstdint>
#include <cstddef>

typedef unsigned long long ull;

#define TSTEPS 1024
#define GDIM   1024
#define HSEQ   ((size_t)TSTEPS * 256 * 256)

__device__ float g_xpb[(size_t)TSTEPS * 256 * GDIM];   // x@W_ih + bias

__device__ __forceinline__ uint32_t packh2(float lo, float hi) {
    uint32_t u;
    asm("cvt.rn.f16x2.f32 %0, %1, %2;" : "=r"(u) : "f"(hi), "f"(lo));
    return u;
}
__device__ __forceinline__ uint32_t sptr(const void* p) {
    return (uint32_t)__cvta_generic_to_shared(p);
}
__device__ __forceinline__ void ldsm4(uint32_t a[4], uint32_t addr) {
    asm volatile("ldmatrix.sync.aligned.m8n8.x4.shared.b16 {%0,%1,%2,%3}, [%4];"
        : "=r"(a[0]), "=r"(a[1]), "=r"(a[2]), "=r"(a[3]) : "r"(addr));
}
__device__ __forceinline__ void mma_f16(float c[4], const uint32_t a[4], uint32_t b0, uint32_t b1) {
    asm volatile("mma.sync.aligned.m16n8k16.row.col.f32.f16.f16.f32 "
        "{%0,%1,%2,%3}, {%4,%5,%6,%7}, {%8,%9}, {%0,%1,%2,%3};"
        : "+f"(c[0]), "+f"(c[1]), "+f"(c[2]), "+f"(c[3])
        : "r"(a[0]), "r"(a[1]), "r"(a[2]), "r"(a[3]), "r"(b0), "r"(b1));
}
__device__ __forceinline__ float sigf(float x) { return 1.f / (1.f + __expf(-x)); }
__device__ __forceinline__ uint32_t mapa_rank(uint32_t addr, uint32_t rank) {
    uint32_t r;
    asm("mapa.shared::cluster.u32 %0, %1, %2;" : "=r"(r) : "r"(addr), "r"(rank));
    return r;
}
__device__ __forceinline__ void mbar_init(uint32_t a, uint32_t cnt) {
    asm volatile("mbarrier.init.shared.b64 [%0], %1;" :: "r"(a), "r"(cnt) : "memory");
}
__device__ __forceinline__ void mbar_expect(uint32_t a, uint32_t bytes) {
    asm volatile("mbarrier.arrive.expect_tx.shared.b64 _, [%0], %1;" :: "r"(a), "r"(bytes) : "memory");
}
__device__ __forceinline__ void mbar_wait(uint32_t a, uint32_t parity) {
    asm volatile(
        "{\n\t.reg .pred P;\n\t"
        "WL_%=:\n\t"
        "mbarrier.try_wait.parity.acquire.cta.shared::cta.b64 P, [%0], %1, 0x989680;\n\t"
        "@P bra.uni WD_%=;\n\t"
        "bra.uni WL_%=;\n\t"
        "WD_%=:\n\t}"
        :: "r"(a), "r"(parity) : "memory");
}
__device__ __forceinline__ void bulk_s2s(uint32_t dst, uint32_t src, uint32_t bytes, uint32_t mbar) {
    asm volatile("cp.async.bulk.shared::cluster.shared::cta.mbarrier::complete_tx::bytes "
                 "[%0], [%1], %2, [%3];"
        :: "r"(dst), "r"(src), "r"(bytes), "r"(mbar) : "memory");
}

// ============================================================================
// Projection: g_xpb = X(262144x256) @ W_ih(256x1024) + bias, fp16 mma
// CTA tile 128M x 128N, 8 warps (2m x 4n), warp tile 64x32, K chunks of 64.
// A: fp16 rows of 144B (64 h + pad), conflict-free ldsm.
// B: k-paired u32 rows [32 x 136], conflict-free b-frag LDS.
// ============================================================================
#define PA_ROWB 144
#define PB_ROWW 136
#define PROJ_A_BYTES (128 * PA_ROWB)               // 18432
#define PROJ_SMEM    (PROJ_A_BYTES + 32 * PB_ROWW * 4)  // 35840

__global__ void __launch_bounds__(256) proj_kernel(const float* __restrict__ X,
                                                   const float* __restrict__ W,
                                                   const float* __restrict__ bias) {
    extern __shared__ char smc[];
    char* Asm = smc;
    uint32_t* Bs32 = (uint32_t*)(smc + PROJ_A_BYTES);
    const int tid = threadIdx.x;
    const int nb = blockIdx.x * 128, mb = blockIdx.y * 128;
    const int w = tid >> 5, lane = tid & 31;
    const int g = lane >> 2, t4 = lane & 3;
    const int mw = w & 1, nw = w >> 1;

    float acc[4][4][4] = {};
    const uint32_t abase = sptr(Asm) + (uint32_t)((mw * 64 + (lane & 15)) * PA_ROWB
                         + (lane >> 4) * 16);

    for (int kc = 0; kc < 4; kc++) {
        if (kc) __syncthreads();
        // stage A 128x64 -> fp16 (8 float4 per thread)
        #pragma unroll
        for (int i = 0; i < 8; i++) {
            int idx = tid + 256 * i, r = idx >> 4, c4 = idx & 15;
            float4 v = *(const float4*)(X + (size_t)(mb + r) * 256 + kc * 64 + c4 * 4);
            *(uint2*)(Asm + r * PA_ROWB + c4 * 8) =
                make_uint2(packh2(v.x, v.y), packh2(v.z, v.w));
        }
        // stage B 64x128 -> k-paired fp16 u32 (4 tasks per thread)
        #pragma unroll
        for (int i = 0; i < 4; i++) {
            int idx = tid + 256 * i, kk = idx >> 5, c4g = idx & 31;
            const float* w0 = W + (size_t)(kc * 64 + 2 * kk) * GDIM + nb + c4g * 4;
            float4 v0 = *(const float4*)w0;
            float4 v1 = *(const float4*)(w0 + GDIM);
            *(uint4*)(Bs32 + kk * PB_ROWW + c4g * 4) =
                make_uint4(packh2(v0.x, v1.x), packh2(v0.y, v1.y),
                           packh2(v0.z, v1.z), packh2(v0.w, v1.w));
        }
        __syncthreads();
        #pragma unroll
        for (int kt = 0; kt < 4; kt++) {
            uint32_t af[4][4];
            #pragma unroll
            for (int mt = 0; mt < 4; mt++)
                ldsm4(af[mt], abase + (uint32_t)(mt * 16 * PA_ROWB) + kt * 32);
            #pragma unroll
            for (int nt = 0; nt < 4; nt++) {
                int col = nw * 32 + nt * 8 + g;
                uint32_t b0 = Bs32[(kt * 8 + t4) * PB_ROWW + col];
                uint32_t b1 = Bs32[(kt * 8 + 4 + t4) * PB_ROWW + col];
                #pragma unroll
                for (int mt = 0; mt < 4; mt++) mma_f16(acc[mt][nt], af[mt], b0, b1);
            }
        }
    }
    #pragma unroll
    for (int mt = 0; mt < 4; mt++) {
        size_t r0 = (size_t)(mb + mw * 64 + mt * 16 + g);
        #pragma unroll
        for (int nt = 0; nt < 4; nt++) {
            int col = nb + nw * 32 + nt * 8 + 2 * t4;
            float b0 = __ldg(bias + col), b1 = __ldg(bias + col + 1);
            *(float2*)(g_xpb + r0 * GDIM + col) =
                make_float2(acc[mt][nt][0] + b0, acc[mt][nt][1] + b1);
            *(float2*)(g_xpb + (r0 + 8) * GDIM + col) =
                make_float2(acc[mt][nt][2] + b0, acc[mt][nt][3] + b1);
        }
    }
}

// ============================================================================
// Recurrence: UNCHANGED from R10 (verified: 2566us, rel_err 3.0959e-4).
// ============================================================================
#define GSTR 132
#define AS_B(gi,b)  (((gi)*2+(b))*8192)
#define GS_B(gi)    (32768 + (gi)*8448)
#define ST_B(gi)    (49664 + (gi)*1024)
#define MB_B        51712
#define LSMEM_BYTES 51744

__global__ void __launch_bounds__(256, 1) __cluster_dims__(8, 1, 1)
lstm_kernel(const float* __restrict__ Whh, float* __restrict__ out, int tail) {
    extern __shared__ char smc[];
    const uint32_t smem0 = sptr(smc);
    const int tid = threadIdx.x;
    const int w = tid >> 5, lane = tid & 31;
    const int g = lane >> 2, t4 = lane & 3;
    const int cid = blockIdx.x >> 3;
    uint32_t r; asm("mov.u32 %0, %%cluster_ctarank;" : "=r"(r));

    if (tid == 0) {
        #pragma unroll
        for (int i = 0; i < 4; i++) mbar_init(smem0 + MB_B + i * 8, 1);
        #pragma unroll
        for (int i = 0; i < 4; i++) mbar_expect(smem0 + MB_B + i * 8, 8192);
    }

    uint32_t bf[16][2][2];
    #pragma unroll
    for (int kt = 0; kt < 16; kt++)
        #pragma unroll
        for (int nt = 0; nt < 2; nt++) {
            int l = w * 16 + nt * 8 + g;
            int gcol = (l >> 5) * 256 + (int)r * 32 + (l & 31);
            bf[kt][nt][0] = packh2(Whh[(size_t)(kt * 16 + 2 * t4) * GDIM + gcol],
                                   Whh[(size_t)(kt * 16 + 2 * t4 + 1) * GDIM + gcol]);
            bf[kt][nt][1] = packh2(Whh[(size_t)(kt * 16 + 8 + 2 * t4) * GDIM + gcol],
                                   Whh[(size_t)(kt * 16 + 8 + 2 * t4 + 1) * GDIM + gcol]);
        }
    __syncthreads();
    asm volatile("barrier.cluster.arrive.aligned;" ::: "memory");
    asm volatile("barrier.cluster.wait.aligned;" ::: "memory");

    const uint32_t laneoff = (uint32_t)((lane >> 4) * 256 + (lane & 15) * 16);
    const int prow = tid >> 4;
    const int pc = (tid & 15) * 2;
    const uint32_t stoff = (uint32_t)((pc >> 3) * 256 + prow * 16 + (pc & 7) * 2);
    float cst[2][2] = {};
    int ph[2][2] = {{0, 0}, {0, 0}};

    for (int t = 0; t < TSTEPS; t++) {
        const int b = t & 1, nbuf = b ^ 1;
        float2 xp[2][4];
        #pragma unroll
        for (int gi = 0; gi < 2; gi++) {
            const float* xr = g_xpb + (size_t)t * (256 * GDIM)
                            + (size_t)(cid * 32 + gi * 16 + prow) * GDIM + r * 32 + pc;
            xp[gi][0] = __ldcg((const float2*)xr);
            xp[gi][1] = __ldcg((const float2*)(xr + 256));
            xp[gi][2] = __ldcg((const float2*)(xr + 512));
            xp[gi][3] = __ldcg((const float2*)(xr + 768));
        }
        #pragma unroll
        for (int gi = 0; gi < 2; gi++) {
            float acc[2][4] = {}, acc2[2][4] = {};
            if (t) {
                uint32_t mb = smem0 + MB_B + (gi * 2 + b) * 8;
                mbar_wait(mb, (uint32_t)ph[gi][b]);
                ph[gi][b] ^= 1;
                if (tid == 0) mbar_expect(mb, 8192);
                uint32_t ab = smem0 + (uint32_t)AS_B(gi, b) + laneoff;
                #pragma unroll
                for (int kt = 0; kt < 8; kt++) {
                    uint32_t a[4];
                    ldsm4(a, ab + (uint32_t)(kt * 512));
                    mma_f16(acc[0], a, bf[kt][0][0], bf[kt][0][1]);
                    mma_f16(acc[1], a, bf[kt][1][0], bf[kt][1][1]);
                }
                #pragma unroll
                for (int kt = 8; kt < 16; kt++) {
                    uint32_t a[4];
                    ldsm4(a, ab + (uint32_t)(kt * 512));
                    mma_f16(acc2[0], a, bf[kt][0][0], bf[kt][0][1]);
                    mma_f16(acc2[1], a, bf[kt][1][0], bf[kt][1][1]);
                }
            }
            float* gsp = (float*)(smc + GS_B(gi));
            #pragma unroll
            for (int nt = 0; nt < 2; nt++) {
                int lc = w * 16 + nt * 8 + 2 * t4;
                *(float2*)&gsp[g * GSTR + lc] =
                    make_float2(acc[nt][0] + acc2[nt][0], acc[nt][1] + acc2[nt][1]);
                *(float2*)&gsp[(g + 8) * GSTR + lc] =
                    make_float2(acc[nt][2] + acc2[nt][2], acc[nt][3] + acc2[nt][3]);
            }
            __syncthreads();
            float2 vi = *(float2*)&gsp[prow * GSTR + pc];
            float2 vf = *(float2*)&gsp[prow * GSTR + 32 + pc];
            float2 vg = *(float2*)&gsp[prow * GSTR + 64 + pc];
            float2 vo = *(float2*)&gsp[prow * GSTR + 96 + pc];
            float i0 = sigf(vi.x + xp[gi][0].x), i1 = sigf(vi.y + xp[gi][0].y);
            float f0 = sigf(vf.x + xp[gi][1].x), f1 = sigf(vf.y + xp[gi][1].y);
            float G0 = tanhf(vg.x + xp[gi][2].x), G1 = tanhf(vg.y + xp[gi][2].y);
            float o0 = sigf(vo.x + xp[gi][3].x), o1 = sigf(vo.y + xp[gi][3].y);
            cst[gi][0] = f0 * cst[gi][0] + i0 * G0;
            cst[gi][1] = f1 * cst[gi][1] + i1 * G1;
            float h0 = o0 * tanhf(cst[gi][0]), h1 = o1 * tanhf(cst[gi][1]);
            *(uint32_t*)(smc + ST_B(gi) + stoff) = packh2(h0, h1);
            __syncthreads();
            if (tid == 0 && t < TSTEPS - 1) {
                asm volatile("fence.proxy.async.shared::cta;" ::: "memory");
                uint32_t src = smem0 + (uint32_t)ST_B(gi);
                uint32_t dstl = smem0 + (uint32_t)AS_B(gi, nbuf) + r * 1024;
                uint32_t mbl = smem0 + MB_B + (gi * 2 + nbuf) * 8;
                #pragma unroll
                for (uint32_t dr = 0; dr < 8; dr++)
                    bulk_s2s(mapa_rank(dstl, dr), src, 1024u, mapa_rank(mbl, dr));
            }
            size_t off = (size_t)(cid * 32 + gi * 16 + prow) * 256 + r * 32 + pc;
            *(float2*)(out + (size_t)t * 65536 + off) = make_float2(h0, h1);
            if (tail && t == TSTEPS - 1) {
                *(float2*)(out + HSEQ + off) = make_float2(h0, h1);
                *(float2*)(out + HSEQ + 65536 + off) = make_float2(cst[gi][0], cst[gi][1]);
            }
        }
    }
    if (tid == 0) {
        asm volatile("cp.async.bulk.commit_group;" ::: "memory");
        asm volatile("cp.async.bulk.wait_group.read 0;" ::: "memory");
    }
    __syncthreads();
    asm volatile("barrier.cluster.arrive.aligned;" ::: "memory");
    asm volatile("barrier.cluster.wait.aligned;" ::: "memory");
}

extern "C" void kernel_launch(void* const* d_in, const int* in_sizes, int n_in,
                              void* d_out, int out_size) {
    const float* x    = (const float*)d_in[0];
    const float* wih  = (const float*)d_in[1];
    const float* whh  = (const float*)d_in[2];
    const float* bias = (const float*)d_in[3];
    float* out = (float*)d_out;
    (void)in_sizes; (void)n_in;
    cudaFuncSetAttribute(proj_kernel, cudaFuncAttributeMaxDynamicSharedMemorySize, PROJ_SMEM);
    cudaFuncSetAttribute(lstm_kernel, cudaFuncAttributeMaxDynamicSharedMemorySize, LSMEM_BYTES);
    proj_kernel<<<dim3(8, 2048), 256, PROJ_SMEM>>>(x, wih, bias);
    int tail = ((size_t)out_size >= HSEQ + 2 * 65536) ? 1 : 0;
    lstm_kernel<<<64, 256, LSMEM_BYTES>>>(whh, out, tail);
}

// round 12
// speedup vs baseline: 1.1345x; 1.1345x over previous
#include <cuda_runtime.h>
#include <cuda_fp16.h>
#include <cstdint>
#include <cstddef>

typedef unsigned long long ull;

#define TSTEPS 1024
#define GDIM   1024
#define HSEQ   ((size_t)TSTEPS * 256 * 256)

__device__ float g_xpb[(size_t)TSTEPS * 256 * GDIM];   // x@W_ih + bias

__device__ __forceinline__ float f2tf(float x) {
    uint32_t r; asm("cvt.rna.tf32.f32 %0, %1;" : "=r"(r) : "f"(x));
    return __uint_as_float(r);
}
__device__ __forceinline__ uint32_t packh2(float lo, float hi) {
    uint32_t u;
    asm("cvt.rn.f16x2.f32 %0, %1, %2;" : "=r"(u) : "f"(hi), "f"(lo));
    return u;
}
__device__ __forceinline__ uint32_t sptr(const void* p) {
    return (uint32_t)__cvta_generic_to_shared(p);
}
__device__ __forceinline__ void ldsm4(uint32_t a[4], uint32_t addr) {
    asm volatile("ldmatrix.sync.aligned.m8n8.x4.shared.b16 {%0,%1,%2,%3}, [%4];"
        : "=r"(a[0]), "=r"(a[1]), "=r"(a[2]), "=r"(a[3]) : "r"(addr));
}
__device__ __forceinline__ void mma_tf32(float c[4], const uint32_t a[4], uint32_t b0, uint32_t b1) {
    asm volatile("mma.sync.aligned.m16n8k8.row.col.f32.tf32.tf32.f32 "
        "{%0,%1,%2,%3}, {%4,%5,%6,%7}, {%8,%9}, {%0,%1,%2,%3};"
        : "+f"(c[0]), "+f"(c[1]), "+f"(c[2]), "+f"(c[3])
        : "r"(a[0]), "r"(a[1]), "r"(a[2]), "r"(a[3]), "r"(b0), "r"(b1));
}
__device__ __forceinline__ void mma_f16(float c[4], const uint32_t a[4], uint32_t b0, uint32_t b1) {
    asm volatile("mma.sync.aligned.m16n8k16.row.col.f32.f16.f16.f32 "
        "{%0,%1,%2,%3}, {%4,%5,%6,%7}, {%8,%9}, {%0,%1,%2,%3};"
        : "+f"(c[0]), "+f"(c[1]), "+f"(c[2]), "+f"(c[3])
        : "r"(a[0]), "r"(a[1]), "r"(a[2]), "r"(a[3]), "r"(b0), "r"(b1));
}
__device__ __forceinline__ float sigf(float x) { return 1.f / (1.f + __expf(-x)); }
__device__ __forceinline__ uint32_t mapa_rank(uint32_t addr, uint32_t rank) {
    uint32_t r;
    asm("mapa.shared::cluster.u32 %0, %1, %2;" : "=r"(r) : "r"(addr), "r"(rank));
    return r;
}
__device__ __forceinline__ void mbar_init(uint32_t a, uint32_t cnt) {
    asm volatile("mbarrier.init.shared.b64 [%0], %1;" :: "r"(a), "r"(cnt) : "memory");
}
__device__ __forceinline__ void mbar_expect(uint32_t a, uint32_t bytes) {
    asm volatile("mbarrier.arrive.expect_tx.shared.b64 _, [%0], %1;" :: "r"(a), "r"(bytes) : "memory");
}
__device__ __forceinline__ void mbar_wait(uint32_t a, uint32_t parity) {
    asm volatile(
        "{\n\t.reg .pred P;\n\t"
        "WL_%=:\n\t"
        "mbarrier.try_wait.parity.acquire.cta.shared::cta.b64 P, [%0], %1, 0x989680;\n\t"
        "@P bra.uni WD_%=;\n\t"
        "bra.uni WL_%=;\n\t"
        "WD_%=:\n\t}"
        :: "r"(a), "r"(parity) : "memory");
}
__device__ __forceinline__ void bulk_s2s(uint32_t dst, uint32_t src, uint32_t bytes, uint32_t mbar) {
    asm volatile("cp.async.bulk.shared::cluster.shared::cta.mbarrier::complete_tx::bytes "
                 "[%0], [%1], %2, [%3];"
        :: "r"(dst), "r"(src), "r"(bytes), "r"(mbar) : "memory");
}
__device__ __forceinline__ void bar_sync(int id, int cnt) {
    asm volatile("bar.sync %0, %1;" :: "r"(id), "r"(cnt) : "memory");
}

// ============================================================================
// Projection: R10 tf32 version verbatim (measured ~0.93ms; fp16 variant was
// slower — reverted).
// ============================================================================
#define PASTR 68
#define PBSTR 136
#define PROJ_SMEM ((128 * PASTR + 64 * PBSTR) * 4)

__global__ void __launch_bounds__(256) proj_kernel(const float* __restrict__ X,
                                                   const float* __restrict__ W,
                                                   const float* __restrict__ bias) {
    extern __shared__ float sm[];
    float* As = sm;
    float* Bs = sm + 128 * PASTR;
    const int tid = threadIdx.x;
    const int nb = blockIdx.x * 128, mb = blockIdx.y * 128;
    const int w = tid >> 5, lane = tid & 31;
    const int g = lane >> 2, t4 = lane & 3;
    const int mw = w & 1, nw = w >> 1;

    float acc[4][4][4] = {};
    const uint32_t abase = sptr(As + (mw * 64 + (lane & 15)) * PASTR + (lane >> 4) * 4);

    for (int kc = 0; kc < 4; kc++) {
        if (kc) __syncthreads();
        #pragma unroll
        for (int i = 0; i < 8; i++) {
            int idx = tid + 256 * i, r = idx >> 4, c4 = idx & 15;
            float4 v = *(const float4*)(X + (size_t)(mb + r) * 256 + kc * 64 + c4 * 4);
            v.x = f2tf(v.x); v.y = f2tf(v.y); v.z = f2tf(v.z); v.w = f2tf(v.w);
            *(float4*)(As + r * PASTR + c4 * 4) = v;
        }
        #pragma unroll
        for (int i = 0; i < 8; i++) {
            int idx = tid + 256 * i, r = idx >> 5, c4 = idx & 31;
            float4 v = *(const float4*)(W + (size_t)(kc * 64 + r) * GDIM + nb + c4 * 4);
            v.x = f2tf(v.x); v.y = f2tf(v.y); v.z = f2tf(v.z); v.w = f2tf(v.w);
            *(float4*)(Bs + r * PBSTR + c4 * 4) = v;
        }
        __syncthreads();
        #pragma unroll
        for (int kt = 0; kt < 8; kt++) {
            uint32_t af[4][4];
            #pragma unroll
            for (int mt = 0; mt < 4; mt++)
                ldsm4(af[mt], abase + (uint32_t)(mt * 16 * PASTR * 4) + kt * 32);
            #pragma unroll
            for (int nt = 0; nt < 4; nt++) {
                int col = nw * 32 + nt * 8 + g;
                uint32_t b0 = __float_as_uint(Bs[(kt * 8 + t4) * PBSTR + col]);
                uint32_t b1 = __float_as_uint(Bs[(kt * 8 + t4 + 4) * PBSTR + col]);
                #pragma unroll
                for (int mt = 0; mt < 4; mt++) mma_tf32(acc[mt][nt], af[mt], b0, b1);
            }
        }
    }
    #pragma unroll
    for (int mt = 0; mt < 4; mt++) {
        size_t r0 = (size_t)(mb + mw * 64 + mt * 16 + g);
        #pragma unroll
        for (int nt = 0; nt < 4; nt++) {
            int col = nb + nw * 32 + nt * 8 + 2 * t4;
            float b0 = __ldg(bias + col), b1 = __ldg(bias + col + 1);
            *(float2*)(g_xpb + r0 * GDIM + col) =
                make_float2(acc[mt][nt][0] + b0, acc[mt][nt][1] + b1);
            *(float2*)(g_xpb + (r0 + 8) * GDIM + col) =
                make_float2(acc[mt][nt][2] + b0, acc[mt][nt][3] + b1);
        }
    }
}

// ============================================================================
// Recurrence: R10 protocol, but the two row-groups run on DISJOINT warp quads
// (warps 0-3 = group 0, warps 4-7 = group 1), fully parallel chains.
// Each group-warp covers all 4 gate blocks (bf[16][4][2]); group-local
// bar.sync; per-group leader re-arms mbar + issues the 8x1KB bulk push.
// SMEM layout identical to R10.
// ============================================================================
#define GSTR 132
#define AS_B(gi,b)  (((gi)*2+(b))*8192)
#define GS_B(gi)    (32768 + (gi)*8448)
#define ST_B(gi)    (49664 + (gi)*1024)
#define MB_B        51712
#define LSMEM_BYTES 51744

__global__ void __launch_bounds__(256, 1) __cluster_dims__(8, 1, 1)
lstm_kernel(const float* __restrict__ Whh, float* __restrict__ out, int tail) {
    extern __shared__ char smc[];
    const uint32_t smem0 = sptr(smc);
    const int tid = threadIdx.x;
    const int w = tid >> 5, lane = tid & 31;
    const int gi = w >> 2;              // group (0/1)
    const int ww = w & 3;               // warp within group
    const int ltid = tid & 127;         // thread within group
    const int g = lane >> 2, t4 = lane & 3;
    const int cid = blockIdx.x >> 3;    // 0..7, rows [32cid, 32cid+32)
    uint32_t r; asm("mov.u32 %0, %%cluster_ctarank;" : "=r"(r));

    if (tid == 0) {
        #pragma unroll
        for (int i = 0; i < 4; i++) mbar_init(smem0 + MB_B + i * 8, 1);
        #pragma unroll
        for (int i = 0; i < 4; i++) mbar_expect(smem0 + MB_B + i * 8, 8192);
    }

    // W_hh fp16 B-fragments: this warp covers gate block ww (all 4 n-tiles)
    uint32_t bf[16][4][2];
    #pragma unroll
    for (int kt = 0; kt < 16; kt++)
        #pragma unroll
        for (int nt = 0; nt < 4; nt++) {
            int l = ww * 32 + nt * 8 + g;                 // 0..127
            int gcol = (l >> 5) * 256 + (int)r * 32 + (l & 31);
            bf[kt][nt][0] = packh2(Whh[(size_t)(kt * 16 + 2 * t4) * GDIM + gcol],
                                   Whh[(size_t)(kt * 16 + 2 * t4 + 1) * GDIM + gcol]);
            bf[kt][nt][1] = packh2(Whh[(size_t)(kt * 16 + 8 + 2 * t4) * GDIM + gcol],
                                   Whh[(size_t)(kt * 16 + 8 + 2 * t4 + 1) * GDIM + gcol]);
        }
    __syncthreads();
    asm volatile("barrier.cluster.arrive.aligned;" ::: "memory");
    asm volatile("barrier.cluster.wait.aligned;" ::: "memory");

    const uint32_t laneoff = (uint32_t)((lane >> 4) * 256 + (lane & 15) * 16);
    // pointwise ownership: 4 h-cols per thread
    const int prow = ltid >> 3;                 // 0..15
    const int pc4 = (ltid & 7) * 4;             // 0,4,...,28
    const uint32_t stoff = (uint32_t)((pc4 >> 3) * 256 + prow * 16 + (pc4 & 7) * 2);
    float c0 = 0.f, c1 = 0.f, c2 = 0.f, c3 = 0.f;
    int ph[2] = {0, 0};

    for (int t = 0; t < TSTEPS; t++) {
        const int b = t & 1, nbuf = b ^ 1;
        // prefetch xp for this group's 4 cols (overlaps wait + mma)
        const float* xr = g_xpb + (size_t)t * (256 * GDIM)
                        + (size_t)(cid * 32 + gi * 16 + prow) * GDIM + (int)r * 32 + pc4;
        float4 x0 = __ldcg((const float4*)xr);
        float4 x1 = __ldcg((const float4*)(xr + 256));
        float4 x2 = __ldcg((const float4*)(xr + 512));
        float4 x3 = __ldcg((const float4*)(xr + 768));

        float acc[4][4] = {}, acc2[4][4] = {};
        if (t) {
            uint32_t mb = smem0 + MB_B + (gi * 2 + b) * 8;
            mbar_wait(mb, (uint32_t)ph[b]);
            ph[b] ^= 1;
            if (ltid == 0) mbar_expect(mb, 8192);
            uint32_t ab = smem0 + (uint32_t)AS_B(gi, b) + laneoff;
            #pragma unroll
            for (int kt = 0; kt < 8; kt++) {
                uint32_t a[4];
                ldsm4(a, ab + (uint32_t)(kt * 512));
                #pragma unroll
                for (int nt = 0; nt < 4; nt++) mma_f16(acc[nt], a, bf[kt][nt][0], bf[kt][nt][1]);
            }
            #pragma unroll
            for (int kt = 8; kt < 16; kt++) {
                uint32_t a[4];
                ldsm4(a, ab + (uint32_t)(kt * 512));
                #pragma unroll
                for (int nt = 0; nt < 4; nt++) mma_f16(acc2[nt], a, bf[kt][nt][0], bf[kt][nt][1]);
            }
        }
        // scatter gates for this group's gate block
        float* gsp = (float*)(smc + GS_B(gi));
        #pragma unroll
        for (int nt = 0; nt < 4; nt++) {
            int lc = ww * 32 + nt * 8 + 2 * t4;
            *(float2*)&gsp[g * GSTR + lc] =
                make_float2(acc[nt][0] + acc2[nt][0], acc[nt][1] + acc2[nt][1]);
            *(float2*)&gsp[(g + 8) * GSTR + lc] =
                make_float2(acc[nt][2] + acc2[nt][2], acc[nt][3] + acc2[nt][3]);
        }
        bar_sync(1 + gi, 128);
        // pointwise: 4 h values
        float4 vi = *(float4*)&gsp[prow * GSTR + pc4];
        float4 vf = *(float4*)&gsp[prow * GSTR + 32 + pc4];
        float4 vg = *(float4*)&gsp[prow * GSTR + 64 + pc4];
        float4 vo = *(float4*)&gsp[prow * GSTR + 96 + pc4];
        float i0 = sigf(vi.x + x0.x), i1 = sigf(vi.y + x0.y);
        float i2 = sigf(vi.z + x0.z), i3 = sigf(vi.w + x0.w);
        float f0 = sigf(vf.x + x1.x), f1 = sigf(vf.y + x1.y);
        float f2 = sigf(vf.z + x1.z), f3 = sigf(vf.w + x1.w);
        float G0 = tanhf(vg.x + x2.x), G1 = tanhf(vg.y + x2.y);
        float G2 = tanhf(vg.z + x2.z), G3 = tanhf(vg.w + x2.w);
        float o0 = sigf(vo.x + x3.x), o1 = sigf(vo.y + x3.y);
        float o2 = sigf(vo.z + x3.z), o3 = sigf(vo.w + x3.w);
        c0 = f0 * c0 + i0 * G0;  c1 = f1 * c1 + i1 * G1;
        c2 = f2 * c2 + i2 * G2;  c3 = f3 * c3 + i3 * G3;
        float h0 = o0 * tanhf(c0), h1 = o1 * tanhf(c1);
        float h2 = o2 * tanhf(c2), h3 = o3 * tanhf(c3);
        // stage fp16 quad into chunk-major block
        *(uint2*)(smc + ST_B(gi) + stoff) = make_uint2(packh2(h0, h1), packh2(h2, h3));
        bar_sync(3 + gi, 128);
        // group leader pushes 8 x 1KB with complete_tx
        if (ltid == 0 && t < TSTEPS - 1) {
            asm volatile("fence.proxy.async.shared::cta;" ::: "memory");
            uint32_t src = smem0 + (uint32_t)ST_B(gi);
            uint32_t dstl = smem0 + (uint32_t)AS_B(gi, nbuf) + r * 1024;
            uint32_t mbl = smem0 + MB_B + (gi * 2 + nbuf) * 8;
            #pragma unroll
            for (uint32_t dr = 0; dr < 8; dr++)
                bulk_s2s(mapa_rank(dstl, dr), src, 1024u, mapa_rank(mbl, dr));
        }
        // stream h out (off critical path)
        size_t off = (size_t)(cid * 32 + gi * 16 + prow) * 256 + (int)r * 32 + pc4;
        *(float4*)(out + (size_t)t * 65536 + off) = make_float4(h0, h1, h2, h3);
        if (tail && t == TSTEPS - 1) {
            *(float4*)(out + HSEQ + off) = make_float4(h0, h1, h2, h3);
            *(float4*)(out + HSEQ + 65536 + off) = make_float4(c0, c1, c2, c3);
        }
    }
    if (ltid == 0) {
        asm volatile("cp.async.bulk.commit_group;" ::: "memory");
        asm volatile("cp.async.bulk.wait_group.read 0;" ::: "memory");
    }
    __syncthreads();
    asm volatile("barrier.cluster.arrive.aligned;" ::: "memory");
    asm volatile("barrier.cluster.wait.aligned;" ::: "memory");
}

extern "C" void kernel_launch(void* const* d_in, const int* in_sizes, int n_in,
                              void* d_out, int out_size) {
    const float* x    = (const float*)d_in[0];
    const float* wih  = (const float*)d_in[1];
    const float* whh  = (const float*)d_in[2];
    const float* bias = (const float*)d_in[3];
    float* out = (float*)d_out;
    (void)in_sizes; (void)n_in;
    cudaFuncSetAttribute(proj_kernel, cudaFuncAttributeMaxDynamicSharedMemorySize, PROJ_SMEM);
    cudaFuncSetAttribute(lstm_kernel, cudaFuncAttributeMaxDynamicSharedMemorySize, LSMEM_BYTES);
    proj_kernel<<<dim3(8, 2048), 256, PROJ_SMEM>>>(x, wih, bias);
    int tail = ((size_t)out_size >= HSEQ + 2 * 65536) ? 1 : 0;
    lstm_kernel<<<64, 256, LSMEM_BYTES>>>(whh, out, tail);
}

// round 13
// speedup vs baseline: 1.1677x; 1.0293x over previous
#include <cuda_runtime.h>
#include <cuda_fp16.h>
#include <cstdint>
#include <cstddef>

typedef unsigned long long ull;

#define TSTEPS 1024
#define GDIM   1024
#define HSEQ   ((size_t)TSTEPS * 256 * 256)

__device__ float g_xpb[(size_t)TSTEPS * 256 * GDIM];   // x@W_ih + bias

__device__ __forceinline__ uint32_t packh2(float lo, float hi) {
    uint32_t u;
    asm("cvt.rn.f16x2.f32 %0, %1, %2;" : "=r"(u) : "f"(hi), "f"(lo));
    return u;
}
__device__ __forceinline__ uint32_t sptr(const void* p) {
    return (uint32_t)__cvta_generic_to_shared(p);
}
__device__ __forceinline__ void ldsm4(uint32_t a[4], uint32_t addr) {
    asm volatile("ldmatrix.sync.aligned.m8n8.x4.shared.b16 {%0,%1,%2,%3}, [%4];"
        : "=r"(a[0]), "=r"(a[1]), "=r"(a[2]), "=r"(a[3]) : "r"(addr));
}
__device__ __forceinline__ void mma_tf32(float c[4], const uint32_t a[4], uint32_t b0, uint32_t b1) {
    asm volatile("mma.sync.aligned.m16n8k8.row.col.f32.tf32.tf32.f32 "
        "{%0,%1,%2,%3}, {%4,%5,%6,%7}, {%8,%9}, {%0,%1,%2,%3};"
        : "+f"(c[0]), "+f"(c[1]), "+f"(c[2]), "+f"(c[3])
        : "r"(a[0]), "r"(a[1]), "r"(a[2]), "r"(a[3]), "r"(b0), "r"(b1));
}
__device__ __forceinline__ void mma_f16(float c[4], const uint32_t a[4], uint32_t b0, uint32_t b1) {
    asm volatile("mma.sync.aligned.m16n8k16.row.col.f32.f16.f16.f32 "
        "{%0,%1,%2,%3}, {%4,%5,%6,%7}, {%8,%9}, {%0,%1,%2,%3};"
        : "+f"(c[0]), "+f"(c[1]), "+f"(c[2]), "+f"(c[3])
        : "r"(a[0]), "r"(a[1]), "r"(a[2]), "r"(a[3]), "r"(b0), "r"(b1));
}
__device__ __forceinline__ float sigf(float x) { return 1.f / (1.f + __expf(-x)); }
__device__ __forceinline__ uint32_t mapa_rank(uint32_t addr, uint32_t rank) {
    uint32_t r;
    asm("mapa.shared::cluster.u32 %0, %1, %2;" : "=r"(r) : "r"(addr), "r"(rank));
    return r;
}
__device__ __forceinline__ void mbar_init(uint32_t a, uint32_t cnt) {
    asm volatile("mbarrier.init.shared.b64 [%0], %1;" :: "r"(a), "r"(cnt) : "memory");
}
__device__ __forceinline__ void mbar_expect(uint32_t a, uint32_t bytes) {
    asm volatile("mbarrier.arrive.expect_tx.shared.b64 _, [%0], %1;" :: "r"(a), "r"(bytes) : "memory");
}
__device__ __forceinline__ void mbar_wait(uint32_t a, uint32_t parity) {
    asm volatile(
        "{\n\t.reg .pred P;\n\t"
        "WL_%=:\n\t"
        "mbarrier.try_wait.parity.acquire.cta.shared::cta.b64 P, [%0], %1, 0x989680;\n\t"
        "@P bra.uni WD_%=;\n\t"
        "bra.uni WL_%=;\n\t"
        "WD_%=:\n\t}"
        :: "r"(a), "r"(parity) : "memory");
}
__device__ __forceinline__ void bulk_s2s(uint32_t dst, uint32_t src, uint32_t bytes, uint32_t mbar) {
    asm volatile("cp.async.bulk.shared::cluster.shared::cta.mbarrier::complete_tx::bytes "
                 "[%0], [%1], %2, [%3];"
        :: "r"(dst), "r"(src), "r"(bytes), "r"(mbar) : "memory");
}
__device__ __forceinline__ void bar_sync(int id, int cnt) {
    asm volatile("bar.sync %0, %1;" :: "r"(id), "r"(cnt) : "memory");
}
__device__ __forceinline__ void cpa16(uint32_t dst, const float* src) {
    asm volatile("cp.async.cg.shared.global [%0], [%1], 16;" :: "r"(dst), "l"(src) : "memory");
}

// ============================================================================
// Projection v3: cp.async double-buffered K-pipeline, tf32 mma (HW-truncated
// inputs). CTA tile 128x128, 8 warps (2m x 4n), K chunks of 32, 2 buffers.
// ============================================================================
#define ASTR 36
#define BSTR 136
#define BUF_FLOATS (128 * ASTR + 32 * BSTR)          // 8960
#define PROJ_SMEM  (2 * BUF_FLOATS * 4)              // 71680

__global__ void __launch_bounds__(256) proj_kernel(const float* __restrict__ X,
                                                   const float* __restrict__ W,
                                                   const float* __restrict__ bias) {
    extern __shared__ float sm[];
    const int tid = threadIdx.x;
    const int nb = blockIdx.x * 128, mb = blockIdx.y * 128;
    const int w = tid >> 5, lane = tid & 31;
    const int g = lane >> 2, t4 = lane & 3;
    const int mw = w & 1, nw = w >> 1;

    // staging task indices (fixed per thread)
    const int a_r = tid >> 3, a_c4 = tid & 7;     // A: 4 rows strided by 32... (idx>>3 covers 0..127 over i)
    const int b_r = tid >> 5, b_c4 = tid & 31;    // B rows 0..7 (+8i)

    float acc[4][4][4] = {};
    const uint32_t abyte = (uint32_t)((mw * 64 + (lane & 15)) * ASTR * 4 + (lane >> 4) * 16);

    // stage chunk kc into buffer buf
    auto stage = [&](int kc, int buf) {
        float* As = sm + buf * BUF_FLOATS;
        float* Bs = As + 128 * ASTR;
        #pragma unroll
        for (int i = 0; i < 4; i++) {
            int r = a_r + 32 * i;
            cpa16(sptr(As + r * ASTR + a_c4 * 4),
                  X + (size_t)(mb + r) * 256 + kc * 32 + a_c4 * 4);
        }
        #pragma unroll
        for (int i = 0; i < 4; i++) {
            int r = b_r + 8 * i;
            cpa16(sptr(Bs + r * BSTR + b_c4 * 4),
                  W + (size_t)(kc * 32 + r) * GDIM + nb + b_c4 * 4);
        }
        asm volatile("cp.async.commit_group;" ::: "memory");
    };

    stage(0, 0);
    #pragma unroll 1
    for (int kc = 0; kc < 8; kc++) {
        if (kc < 7) stage(kc + 1, (kc + 1) & 1);
        if (kc < 7) asm volatile("cp.async.wait_group 1;" ::: "memory");
        else        asm volatile("cp.async.wait_group 0;" ::: "memory");
        __syncthreads();
        float* As = sm + (kc & 1) * BUF_FLOATS;
        float* Bs = As + 128 * ASTR;
        const uint32_t abase = sptr(As) + abyte;
        #pragma unroll
        for (int kt = 0; kt < 4; kt++) {
            uint32_t af[4][4];
            #pragma unroll
            for (int mt = 0; mt < 4; mt++)
                ldsm4(af[mt], abase + (uint32_t)(mt * 16 * ASTR * 4) + kt * 32);
            #pragma unroll
            for (int nt = 0; nt < 4; nt++) {
                int col = nw * 32 + nt * 8 + g;
                uint32_t b0 = __float_as_uint(Bs[(kt * 8 + t4) * BSTR + col]);
                uint32_t b1 = __float_as_uint(Bs[(kt * 8 + t4 + 4) * BSTR + col]);
                #pragma unroll
                for (int mt = 0; mt < 4; mt++) mma_tf32(acc[mt][nt], af[mt], b0, b1);
            }
        }
        __syncthreads();   // buffer consumed; safe for next-next stage
    }
    #pragma unroll
    for (int mt = 0; mt < 4; mt++) {
        size_t r0 = (size_t)(mb + mw * 64 + mt * 16 + g);
        #pragma unroll
        for (int nt = 0; nt < 4; nt++) {
            int col = nb + nw * 32 + nt * 8 + 2 * t4;
            float b0 = __ldg(bias + col), b1 = __ldg(bias + col + 1);
            *(float2*)(g_xpb + r0 * GDIM + col) =
                make_float2(acc[mt][nt][0] + b0, acc[mt][nt][1] + b1);
            *(float2*)(g_xpb + (r0 + 8) * GDIM + col) =
                make_float2(acc[mt][nt][2] + b0, acc[mt][nt][3] + b1);
        }
    }
}

// ============================================================================
// Recurrence: UNCHANGED from R12 (verified: 2307us, rel_err 3.0959e-4).
// ============================================================================
#define GSTR 132
#define AS_B(gi,b)  (((gi)*2+(b))*8192)
#define GS_B(gi)    (32768 + (gi)*8448)
#define ST_B(gi)    (49664 + (gi)*1024)
#define MB_B        51712
#define LSMEM_BYTES 51744

__global__ void __launch_bounds__(256, 1) __cluster_dims__(8, 1, 1)
lstm_kernel(const float* __restrict__ Whh, float* __restrict__ out, int tail) {
    extern __shared__ char smc[];
    const uint32_t smem0 = sptr(smc);
    const int tid = threadIdx.x;
    const int w = tid >> 5, lane = tid & 31;
    const int gi = w >> 2;
    const int ww = w & 3;
    const int ltid = tid & 127;
    const int g = lane >> 2, t4 = lane & 3;
    const int cid = blockIdx.x >> 3;
    uint32_t r; asm("mov.u32 %0, %%cluster_ctarank;" : "=r"(r));

    if (tid == 0) {
        #pragma unroll
        for (int i = 0; i < 4; i++) mbar_init(smem0 + MB_B + i * 8, 1);
        #pragma unroll
        for (int i = 0; i < 4; i++) mbar_expect(smem0 + MB_B + i * 8, 8192);
    }

    uint32_t bf[16][4][2];
    #pragma unroll
    for (int kt = 0; kt < 16; kt++)
        #pragma unroll
        for (int nt = 0; nt < 4; nt++) {
            int l = ww * 32 + nt * 8 + g;
            int gcol = (l >> 5) * 256 + (int)r * 32 + (l & 31);
            bf[kt][nt][0] = packh2(Whh[(size_t)(kt * 16 + 2 * t4) * GDIM + gcol],
                                   Whh[(size_t)(kt * 16 + 2 * t4 + 1) * GDIM + gcol]);
            bf[kt][nt][1] = packh2(Whh[(size_t)(kt * 16 + 8 + 2 * t4) * GDIM + gcol],
                                   Whh[(size_t)(kt * 16 + 8 + 2 * t4 + 1) * GDIM + gcol]);
        }
    __syncthreads();
    asm volatile("barrier.cluster.arrive.aligned;" ::: "memory");
    asm volatile("barrier.cluster.wait.aligned;" ::: "memory");

    const uint32_t laneoff = (uint32_t)((lane >> 4) * 256 + (lane & 15) * 16);
    const int prow = ltid >> 3;
    const int pc4 = (ltid & 7) * 4;
    const uint32_t stoff = (uint32_t)((pc4 >> 3) * 256 + prow * 16 + (pc4 & 7) * 2);
    float c0 = 0.f, c1 = 0.f, c2 = 0.f, c3 = 0.f;
    int ph[2] = {0, 0};

    for (int t = 0; t < TSTEPS; t++) {
        const int b = t & 1, nbuf = b ^ 1;
        const float* xr = g_xpb + (size_t)t * (256 * GDIM)
                        + (size_t)(cid * 32 + gi * 16 + prow) * GDIM + (int)r * 32 + pc4;
        float4 x0 = __ldcg((const float4*)xr);
        float4 x1 = __ldcg((const float4*)(xr + 256));
        float4 x2 = __ldcg((const float4*)(xr + 512));
        float4 x3 = __ldcg((const float4*)(xr + 768));

        float acc[4][4] = {}, acc2[4][4] = {};
        if (t) {
            uint32_t mb = smem0 + MB_B + (gi * 2 + b) * 8;
            mbar_wait(mb, (uint32_t)ph[b]);
            ph[b] ^= 1;
            if (ltid == 0) mbar_expect(mb, 8192);
            uint32_t ab = smem0 + (uint32_t)AS_B(gi, b) + laneoff;
            #pragma unroll
            for (int kt = 0; kt < 8; kt++) {
                uint32_t a[4];
                ldsm4(a, ab + (uint32_t)(kt * 512));
                #pragma unroll
                for (int nt = 0; nt < 4; nt++) mma_f16(acc[nt], a, bf[kt][nt][0], bf[kt][nt][1]);
            }
            #pragma unroll
            for (int kt = 8; kt < 16; kt++) {
                uint32_t a[4];
                ldsm4(a, ab + (uint32_t)(kt * 512));
                #pragma unroll
                for (int nt = 0; nt < 4; nt++) mma_f16(acc2[nt], a, bf[kt][nt][0], bf[kt][nt][1]);
            }
        }
        float* gsp = (float*)(smc + GS_B(gi));
        #pragma unroll
        for (int nt = 0; nt < 4; nt++) {
            int lc = ww * 32 + nt * 8 + 2 * t4;
            *(float2*)&gsp[g * GSTR + lc] =
                make_float2(acc[nt][0] + acc2[nt][0], acc[nt][1] + acc2[nt][1]);
            *(float2*)&gsp[(g + 8) * GSTR + lc] =
                make_float2(acc[nt][2] + acc2[nt][2], acc[nt][3] + acc2[nt][3]);
        }
        bar_sync(1 + gi, 128);
        float4 vi = *(float4*)&gsp[prow * GSTR + pc4];
        float4 vf = *(float4*)&gsp[prow * GSTR + 32 + pc4];
        float4 vg = *(float4*)&gsp[prow * GSTR + 64 + pc4];
        float4 vo = *(float4*)&gsp[prow * GSTR + 96 + pc4];
        float i0 = sigf(vi.x + x0.x), i1 = sigf(vi.y + x0.y);
        float i2 = sigf(vi.z + x0.z), i3 = sigf(vi.w + x0.w);
        float f0 = sigf(vf.x + x1.x), f1 = sigf(vf.y + x1.y);
        float f2 = sigf(vf.z + x1.z), f3 = sigf(vf.w + x1.w);
        float G0 = tanhf(vg.x + x2.x), G1 = tanhf(vg.y + x2.y);
        float G2 = tanhf(vg.z + x2.z), G3 = tanhf(vg.w + x2.w);
        float o0 = sigf(vo.x + x3.x), o1 = sigf(vo.y + x3.y);
        float o2 = sigf(vo.z + x3.z), o3 = sigf(vo.w + x3.w);
        c0 = f0 * c0 + i0 * G0;  c1 = f1 * c1 + i1 * G1;
        c2 = f2 * c2 + i2 * G2;  c3 = f3 * c3 + i3 * G3;
        float h0 = o0 * tanhf(c0), h1 = o1 * tanhf(c1);
        float h2 = o2 * tanhf(c2), h3 = o3 * tanhf(c3);
        *(uint2*)(smc + ST_B(gi) + stoff) = make_uint2(packh2(h0, h1), packh2(h2, h3));
        bar_sync(3 + gi, 128);
        if (ltid == 0 && t < TSTEPS - 1) {
            asm volatile("fence.proxy.async.shared::cta;" ::: "memory");
            uint32_t src = smem0 + (uint32_t)ST_B(gi);
            uint32_t dstl = smem0 + (uint32_t)AS_B(gi, nbuf) + r * 1024;
            uint32_t mbl = smem0 + MB_B + (gi * 2 + nbuf) * 8;
            #pragma unroll
            for (uint32_t dr = 0; dr < 8; dr++)
                bulk_s2s(mapa_rank(dstl, dr), src, 1024u, mapa_rank(mbl, dr));
        }
        size_t off = (size_t)(cid * 32 + gi * 16 + prow) * 256 + (int)r * 32 + pc4;
        *(float4*)(out + (size_t)t * 65536 + off) = make_float4(h0, h1, h2, h3);
        if (tail && t == TSTEPS - 1) {
            *(float4*)(out + HSEQ + off) = make_float4(h0, h1, h2, h3);
            *(float4*)(out + HSEQ + 65536 + off) = make_float4(c0, c1, c2, c3);
        }
    }
    if (ltid == 0) {
        asm volatile("cp.async.bulk.commit_group;" ::: "memory");
        asm volatile("cp.async.bulk.wait_group.read 0;" ::: "memory");
    }
    __syncthreads();
    asm volatile("barrier.cluster.arrive.aligned;" ::: "memory");
    asm volatile("barrier.cluster.wait.aligned;" ::: "memory");
}

extern "C" void kernel_launch(void* const* d_in, const int* in_sizes, int n_in,
                              void* d_out, int out_size) {
    const float* x    = (const float*)d_in[0];
    const float* wih  = (const float*)d_in[1];
    const float* whh  = (const float*)d_in[2];
    const float* bias = (const float*)d_in[3];
    float* out = (float*)d_out;
    (void)in_sizes; (void)n_in;
    cudaFuncSetAttribute(proj_kernel, cudaFuncAttributeMaxDynamicSharedMemorySize, PROJ_SMEM);
    cudaFuncSetAttribute(lstm_kernel, cudaFuncAttributeMaxDynamicSharedMemorySize, LSMEM_BYTES);
    proj_kernel<<<dim3(8, 2048), 256, PROJ_SMEM>>>(x, wih, bias);
    int tail = ((size_t)out_size >= HSEQ + 2 * 65536) ? 1 : 0;
    lstm_kernel<<<64, 256, LSMEM_BYTES>>>(whh, out, tail);
}